// round 10
// baseline (speedup 1.0000x reference)
#include <cuda_runtime.h>

// SSIM loss, (32,1,512,512) fp32. Single fused kernel, vertical-first FIR.
// R8 = R6 + packed u64 staging of the xy v-conv plane (STS.64/LDS.64, no
//      inner-loop packs). Product channel stays scalar (R7's pair-packing
//      regressed: inner-loop MOV packs cost more slots than the FMAs saved).

#define IMG   512
#define TW    64
#define TH    32
#define VC    74          // v-conv cols staged (TW + 10)
#define PIT   75          // pitch: f32 stride 11 mod 32; u64 stride 22 mod 32 (both clean)
#define GX    8
#define GY    16
#define GZ    32
#define NBLK  (GX * GY * GZ)   // 4096

__device__ float        g_partials[NBLK];
__device__ unsigned int g_count;     // zero-init; self-resets

// normalized 1D Gaussian, K=11, sigma=1.5
#define W0 0.00102838f
#define W1 0.00759876f
#define W2 0.03600077f
#define W3 0.10936060f
#define W4 0.21300553f
#define W5 0.26601172f

#define FMA2(d, a, b, c) \
    asm("fma.rn.f32x2 %0, %1, %2, %3;" : "=l"(d) : "l"(a), "l"(b), "l"(c))
#define UNPK(lo, hi, v) \
    asm("mov.b64 {%0, %1}, %2;" : "=f"(lo), "=f"(hi) : "l"(v))
#define PK(v, lo, hi) \
    asm("mov.b64 %0, {%1, %2};" : "=l"(v) : "f"(lo), "f"(hi))

__device__ __forceinline__ unsigned long long pk2(float w) {
    unsigned long long r;
    asm("mov.b64 %0, {%1, %1};" : "=l"(r) : "f"(w));
    return r;
}

__global__ __launch_bounds__(256, 5)
void ssim_fused_kernel(const float* __restrict__ X, const float* __restrict__ Y,
                       float* __restrict__ out)
{
    __shared__ unsigned long long vxy[TH][PIT];  // packed v-conv (x,y) 18.75KB
    __shared__ float              vp [TH][PIT];  // v-conv of x*y        9.4KB
    __shared__ float              wsum[8];
    __shared__ int                s_last;

    const float WGs[11] = {W0, W1, W2, W3, W4, W5, W4, W3, W2, W1, W0};
    const unsigned long long p0 = pk2(W0), p1 = pk2(W1), p2 = pk2(W2),
                             p3 = pk2(W3), p4 = pk2(W4), p5 = pk2(W5);
    const unsigned long long WP[11] = {p0,p1,p2,p3,p4,p5,p4,p3,p2,p1,p0};

    const int tid  = threadIdx.x;
    const int img  = blockIdx.z;
    const int row0 = blockIdx.y * TH - 5;
    const int col0 = blockIdx.x * TW - 5;

    const float* __restrict__ Xi = X + (size_t)img * IMG * IMG;
    const float* __restrict__ Yi = Y + (size_t)img * IMG * IMG;

    const bool rowsafe = (row0 >= 0) && (row0 + TH + 9 < IMG);

    // ---- phase 1: vertical streaming FIR from GLOBAL: 296 items ----
    // item = (column c of 74, rowgroup g of 4); 8 outputs, reads 18 rows.
    #pragma unroll 1
    for (int i = tid; i < VC * 4; i += 256) {
        const int c  = i % VC;
        const int g  = i / VC;
        const int gc = col0 + c;
        const int rb = row0 + g * 8;

        unsigned long long acc2[8];
        float accp[8];
        #pragma unroll
        for (int j = 0; j < 8; j++) { acc2[j] = 0ull; accp[j] = 0.0f; }

        if ((unsigned)gc < (unsigned)IMG) {
            const float* __restrict__ px = Xi + gc;
            const float* __restrict__ py = Yi + gc;
            if (rowsafe) {
                #pragma unroll
                for (int m = 0; m < 18; m++) {
                    const int off = (rb + m) * IMG;
                    float xv = __ldg(px + off);
                    float yv = __ldg(py + off);
                    unsigned long long v;
                    PK(v, xv, yv);
                    float pm = xv * yv;
                    #pragma unroll
                    for (int j = 0; j < 8; j++) {
                        const int k = m - j;
                        if (k >= 0 && k <= 10) {
                            FMA2(acc2[j], v, WP[k], acc2[j]);
                            accp[j] = fmaf(WGs[k], pm, accp[j]);
                        }
                    }
                }
            } else {
                #pragma unroll
                for (int m = 0; m < 18; m++) {
                    const int gr = rb + m;
                    float xv = 0.0f, yv = 0.0f;
                    if ((unsigned)gr < (unsigned)IMG) {
                        xv = __ldg(px + gr * IMG);
                        yv = __ldg(py + gr * IMG);
                    }
                    unsigned long long v;
                    PK(v, xv, yv);
                    float pm = xv * yv;
                    #pragma unroll
                    for (int j = 0; j < 8; j++) {
                        const int k = m - j;
                        if (k >= 0 && k <= 10) {
                            FMA2(acc2[j], v, WP[k], acc2[j]);
                            accp[j] = fmaf(WGs[k], pm, accp[j]);
                        }
                    }
                }
            }
        }
        const int vr = g * 8;
        #pragma unroll
        for (int j = 0; j < 8; j++) {
            vxy[vr + j][c] = acc2[j];    // packed store, no unpack
            vp [vr + j][c] = accp[j];
        }
    }
    __syncthreads();

    // ---- phase 2: horizontal FIR from smem + SSIM: 256 items ----
    // item = (row r of 32, colgroup o of 8); 8 outputs, reads 18 cols.
    const float C1 = 0.0001f, C2 = 0.0009f;
    float lsum = 0.0f;
    {
        const int r  = tid & 31;
        const int c0 = (tid >> 5) * 8;

        unsigned long long acc2[8];
        float accp[8];
        #pragma unroll
        for (int j = 0; j < 8; j++) { acc2[j] = 0ull; accp[j] = 0.0f; }

        #pragma unroll
        for (int m = 0; m < 18; m++) {
            unsigned long long v = vxy[r][c0 + m];   // LDS.64, feeds FMA2 directly
            float pm = vp[r][c0 + m];
            #pragma unroll
            for (int j = 0; j < 8; j++) {
                const int k = m - j;
                if (k >= 0 && k <= 10) {
                    FMA2(acc2[j], v, WP[k], acc2[j]);
                    accp[j] = fmaf(WGs[k], pm, accp[j]);
                }
            }
        }
        #pragma unroll
        for (int j = 0; j < 8; j++) {
            float mu1, mu2;
            UNPK(mu1, mu2, acc2[j]);
            float m12 = mu1 * mu2;
            float sig = accp[j] - m12;
            float sq  = mu1 * mu1 + mu2 * mu2;
            float num = (2.0f * m12 + C1) * (2.0f * sig + C2);
            float den = (sq + C1) * (sq + C2);
            lsum += __fdividef(num, den);
        }
    }

    // ---------------- block reduction ----------------
    #pragma unroll
    for (int off = 16; off > 0; off >>= 1)
        lsum += __shfl_xor_sync(0xFFFFFFFFu, lsum, off);
    if ((tid & 31) == 0) wsum[tid >> 5] = lsum;
    __syncthreads();
    if (tid == 0) {
        float v = 0.0f;
        #pragma unroll
        for (int w = 0; w < 8; w++) v += wsum[w];
        int bid = blockIdx.x + GX * (blockIdx.y + GY * blockIdx.z);
        g_partials[bid] = v;
        __threadfence();
        unsigned int ticket = atomicAdd(&g_count, 1u);
        s_last = (ticket == NBLK - 1);
    }
    __syncthreads();

    // ---------------- last block: final reduction ----------------
    if (s_last) {
        float s = 0.0f;
        #pragma unroll 4
        for (int i = tid; i < NBLK; i += 256)
            s += *((volatile float*)&g_partials[i]);
        #pragma unroll
        for (int off = 16; off > 0; off >>= 1)
            s += __shfl_xor_sync(0xFFFFFFFFu, s, off);
        __syncthreads();
        if ((tid & 31) == 0) wsum[tid >> 5] = s;
        __syncthreads();
        if (tid == 0) {
            float v = 0.0f;
            #pragma unroll
            for (int w = 0; w < 8; w++) v += wsum[w];
            out[0]  = v * (1.0f / 8388608.0f);
            g_count = 0;
        }
    }
}

extern "C" void kernel_launch(void* const* d_in, const int* in_sizes, int n_in,
                              void* d_out, int out_size)
{
    (void)in_sizes; (void)n_in; (void)out_size;
    const float* X_gt   = (const float*)d_in[0];
    const float* X_pred = (const float*)d_in[1];
    float* out = (float*)d_out;

    dim3 grid(GX, GY, GZ);
    ssim_fused_kernel<<<grid, 256>>>(X_gt, X_pred, out);
}